// round 16
// baseline (speedup 1.0000x reference)
#include <cuda_runtime.h>
#include <cuda_fp16.h>
#include <math.h>

// x (32, 1, 720, 1024) f32 -> out (32, 1, 512, 512) f32
// out[z,y,xp] = (pi/720) * sum_v lerp(x[z,0,v,:], t),  t = xf*cos + yf*sin + 511.5
// t in [150.2, 872.8] => always in-bounds for nDct=1024.
//
// R12 = R10 skeleton (TMA window staging, double buffer, one __syncthreads per
// view — the proven sync shape; R11's broadcast mbarrier pipeline reverted)
// with 64-byte detector cells holding 16 z of taps PLUS 16 z of precomputed
// half diffs d[i] = a[i+1]-a[i]:
//   - HSUB2 eliminated from the inner loop (diff precomputed with identical
//     half arithmetic in the convert kernel -> bitwise-same lerp)
//   - ZC=16 amortizes scalar/LDS-issue over 16 z (3.2 slots/sample vs 4.1)
//   - grid stays 1024 CTAs (8 x-tiles x 64 8-row y-tiles x 2 z-groups)

#define NV   720
#define ND   1024
#define NVND (NV * ND)
#define NXI  512
#define NYI  512
#define WIN  72           // window cells/view (8-row tile: span <= 66 + slack)
#define RY   2            // r-steps per thread (y stride 4) -> 8 y rows per warp
#define ZC   16           // z-slices per cell
#define CELLB 64          // 32 B taps + 32 B diffs
#define WINB (WIN * CELLB) // 4608 bytes per view window
#define NBUF 2

__device__ float g_cos[NV];
__device__ float g_sin[NV];
// [zg][v][d] cells of 64 B: {a half[16], diff half[16]}; 2*720*1024*64 B = 94.4 MB
__device__ __align__(16) __half g_hx[2ULL * NV * ND * 32];

// Convert: x[z][v][d] f32 -> cell(zg,v,d) = {half taps for z=zg*16..+15,
// half diffs vs d+1}. Diff uses the same half subtraction the old inner-loop
// HSUB2 did -> identical results. Also fills trig tables.
__global__ __launch_bounds__(256) void convert_kernel(const float* __restrict__ x) {
    const int d  = blockIdx.x * 256 + threadIdx.x;
    const int v  = blockIdx.y;
    const int zg = blockIdx.z;
    if (zg == 0 && blockIdx.x == 0 && threadIdx.x == 0) {
        float th = (float)v * (float)(M_PI / (double)NV);
        g_cos[v] = cosf(th);
        g_sin[v] = sinf(th);
    }
    const int d1 = (d + 1 < ND) ? (d + 1) : (ND - 1);   // clamp; never sampled
    const float* __restrict__ b0 = x + (size_t)(zg * ZC) * NVND + (size_t)v * ND;

    unsigned ta[8], td[8];
#pragma unroll
    for (int j = 0; j < 8; j++) {
        float f0 = b0[(size_t)(2 * j)     * NVND + d];
        float f1 = b0[(size_t)(2 * j + 1) * NVND + d];
        float g0 = b0[(size_t)(2 * j)     * NVND + d1];
        float g1 = b0[(size_t)(2 * j + 1) * NVND + d1];
        __half2 ah = __floats2half2_rn(f0, f1);
        __half2 bh = __floats2half2_rn(g0, g1);
        __half2 dh = __hsub2(bh, ah);
        ta[j] = *reinterpret_cast<unsigned*>(&ah);
        td[j] = *reinterpret_cast<unsigned*>(&dh);
    }
    uint4* o = reinterpret_cast<uint4*>(&g_hx[(((size_t)zg * NV + v) * ND + d) * 32]);
    o[0] = make_uint4(ta[0], ta[1], ta[2], ta[3]);
    o[1] = make_uint4(ta[4], ta[5], ta[6], ta[7]);
    o[2] = make_uint4(td[0], td[1], td[2], td[3]);
    o[3] = make_uint4(td[4], td[5], td[6], td[7]);
}

// Must be computed identically by TMA issuer and consumers (same FP ops => it is).
__device__ __forceinline__ int calc_dmin(float c, float s, float xfmin, float yf0) {
    float xsel = (c >= 0.0f) ? xfmin : (xfmin + 63.0f);   // 64-wide x tile
    float tmin = fmaf(xsel, c, fmaf(yf0, s, 511.5f));     // s >= 0 on [0,pi)
    return (int)tmin - 1;                                 // tmin > 0: trunc==floor; -1 ulp guard
}

__device__ __forceinline__ void mbar_wait(unsigned mbar, unsigned phase) {
    unsigned done;
    do {
        asm volatile(
            "{\n\t.reg .pred p;\n\t"
            "mbarrier.try_wait.parity.acquire.cta.shared::cta.b64 p, [%1], %2, 0x989680;\n\t"
            "selp.b32 %0, 1, 0, p;\n\t}"
            : "=r"(done) : "r"(mbar), "r"(phase) : "memory");
    } while (!done);
}

__device__ __forceinline__ void tma_fill(unsigned dst, const __half* src,
                                         unsigned full_mbar) {
    asm volatile("mbarrier.arrive.expect_tx.shared.b64 _, [%0], %1;"
                 :: "r"(full_mbar), "r"((unsigned)WINB) : "memory");
    asm volatile("cp.async.bulk.shared::cta.global.mbarrier::complete_tx::bytes "
                 "[%0], [%1], %2, [%3];"
                 :: "r"(dst), "l"(src), "r"((unsigned)WINB), "r"(full_mbar)
                 : "memory");
}

__global__ __launch_bounds__(256, 4) void backproject_kernel(
    float* __restrict__ out)
{
    __shared__ __align__(16) char cellraw[NBUF][WINB];   // 9.2 KB
    __shared__ float s_cos[NV], s_sin[NV];               // 5.76 KB
    __shared__ __align__(8) unsigned long long mbar[NBUF];

    const int tid  = threadIdx.x;            // 256 threads = 8 warps
    const int lane = tid & 31;
    const int wrp  = tid >> 5;
    const int lx   = lane & 7;               // 8 x per warp
    const int ly   = lane >> 3;              // 4 y per warp

    for (int i = tid; i < NV; i += 256) { s_cos[i] = g_cos[i]; s_sin[i] = g_sin[i]; }

    const int xg = blockIdx.x * 64 + wrp * 8 + lx;   // 8 x-tiles of 64
    const int yb = blockIdx.y * 8 + ly;              // 64 y-tiles of 8; rows yb + 4r
    const int zg = blockIdx.z;                       // 2 z-groups of 16

    const float xf    = (float)xg - 255.5f;
    const float ybf   = (float)yb - 255.5f;
    const float xfmin = (float)(blockIdx.x * 64) - 255.5f;
    const float yf0   = (float)(blockIdx.y * 8) - 255.5f;

    float acc[RY][ZC];                       // 32 f32 accumulators
#pragma unroll
    for (int r = 0; r < RY; r++)
#pragma unroll
        for (int zz = 0; zz < ZC; zz++) acc[r][zz] = 0.0f;

    unsigned int cell_base, mbar_base;
    asm("{ .reg .u64 t; cvta.to.shared.u64 t, %1; cvt.u32.u64 %0, t; }"
        : "=r"(cell_base) : "l"((const void*)cellraw));
    asm("{ .reg .u64 t; cvta.to.shared.u64 t, %1; cvt.u32.u64 %0, t; }"
        : "=r"(mbar_base) : "l"((const void*)mbar));

    const __half* __restrict__ hz = &g_hx[(size_t)zg * NVND * 32];

    if (tid == 0) {
        asm volatile("mbarrier.init.shared.b64 [%0], 1;" :: "r"(mbar_base)     : "memory");
        asm volatile("mbarrier.init.shared.b64 [%0], 1;" :: "r"(mbar_base + 8) : "memory");
    }
    __syncthreads();   // trig + mbarrier init visible

    if (tid == 0) {
        // Prime views 0 (exact c=1,s=0) and 1.
        int dm0 = calc_dmin(1.0f, 0.0f, xfmin, yf0);
        tma_fill(cell_base, hz + (size_t)dm0 * 32, mbar_base);
        int dm1 = calc_dmin(s_cos[1], s_sin[1], xfmin, yf0);
        tma_fill(cell_base + WINB, hz + ((size_t)ND + dm1) * 32, mbar_base + 8);
    }

    for (int v = 0; v < NV; v++) {
        const int buf = v & 1;
        mbar_wait(mbar_base + buf * 8, (unsigned)((v >> 1) & 1));

        const float c = (v == 0) ? 1.0f : s_cos[v];
        const float s = (v == 0) ? 0.0f : s_sin[v];
        const int dmin = calc_dmin(c, s, xfmin, yf0);
        // u = t - dmin, in [0, WIN-2) for every pixel of this tile
        float u = fmaf(xf, c, fmaf(ybf, s, 511.5f - (float)dmin));
        const float s4 = 4.0f * s;                 // y stride 4 rows per r-step
        const unsigned int base = cell_base + (unsigned)(buf * WINB);

#pragma unroll
        for (int r = 0; r < RY; r++) {
            int   i0 = (int)u;                     // u > 0: trunc == floor
            float w  = u - (float)i0;
            __half2 wh2 = __float2half2_rn(w);     // one F2FP (broadcast pack)
            unsigned int a0 = base + (unsigned)i0 * CELLB;
            uint4 A, A2, D, D2;                    // taps z0..15, diffs z0..15
            asm("ld.shared.v4.b32 {%0,%1,%2,%3}, [%4];"
                : "=r"(A.x),  "=r"(A.y),  "=r"(A.z),  "=r"(A.w)  : "r"(a0));
            asm("ld.shared.v4.b32 {%0,%1,%2,%3}, [%4 + 16];"
                : "=r"(A2.x), "=r"(A2.y), "=r"(A2.z), "=r"(A2.w) : "r"(a0));
            asm("ld.shared.v4.b32 {%0,%1,%2,%3}, [%4 + 32];"
                : "=r"(D.x),  "=r"(D.y),  "=r"(D.z),  "=r"(D.w)  : "r"(a0));
            asm("ld.shared.v4.b32 {%0,%1,%2,%3}, [%4 + 48];"
                : "=r"(D2.x), "=r"(D2.y), "=r"(D2.z), "=r"(D2.w) : "r"(a0));
#pragma unroll
            for (int p = 0; p < 8; p++) {
                unsigned ua = (p == 0) ? A.x  : (p == 1) ? A.y  : (p == 2) ? A.z  :
                              (p == 3) ? A.w  : (p == 4) ? A2.x : (p == 5) ? A2.y :
                              (p == 6) ? A2.z : A2.w;
                unsigned ud = (p == 0) ? D.x  : (p == 1) ? D.y  : (p == 2) ? D.z  :
                              (p == 3) ? D.w  : (p == 4) ? D2.x : (p == 5) ? D2.y :
                              (p == 6) ? D2.z : D2.w;
                __half2 ha = *reinterpret_cast<__half2*>(&ua);
                __half2 hd = *reinterpret_cast<__half2*>(&ud);
                // l = a + w*diff  (diff precomputed == old HSUB2 result)
                __half2 l  = __hfma2(hd, wh2, ha);
                float2 f   = __half22float2(l);
                acc[r][2 * p]     += f.x;
                acc[r][2 * p + 1] += f.y;
            }
            u += s4;
        }

        __syncthreads();   // all threads done reading buf before refilling it

        if (v + 2 < NV && tid == 0) {
            float c2 = s_cos[v + 2], s2 = s_sin[v + 2];
            int dm = calc_dmin(c2, s2, xfmin, yf0);
            tma_fill(base, hz + ((size_t)(v + 2) * ND + dm) * 32, mbar_base + buf * 8);
        }
    }

    const float scale = (float)(M_PI / (double)NV);
#pragma unroll
    for (int r = 0; r < RY; r++) {
        const int y = yb + 4 * r;
#pragma unroll
        for (int zz = 0; zz < ZC; zz++) {
            out[((size_t)(zg * ZC + zz) * NYI + y) * NXI + xg] = acc[r][zz] * scale;
        }
    }
}

extern "C" void kernel_launch(void* const* d_in, const int* in_sizes, int n_in,
                              void* d_out, int out_size)
{
    const float* x   = (const float*)d_in[0];
    float*       out = (float*)d_out;

    convert_kernel<<<dim3(ND / 256, NV, 2), 256>>>(x);

    dim3 grid(8, 64, 2);   // x-tiles, 8-row y-tiles, z-groups = 1024 CTAs
    backproject_kernel<<<grid, 256>>>(out);
}

// round 17
// speedup vs baseline: 2.0535x; 2.0535x over previous
#include <cuda_runtime.h>
#include <cuda_fp16.h>
#include <math.h>

// x (32, 1, 720, 1024) f32 -> out (32, 1, 512, 512) f32
// out[z,y,xp] = (pi/720) * sum_v lerp(x[z,0,v,:], t),  t = xf*cos + yf*sin + 511.5
// t in [150.2, 872.8] => always in-bounds for nDct=1024.
//
// R13 = R10 geometry exactly (ZC=8 z-oct 16-B cells, WIN=80, TMA window
// staging, double buffer + one __syncthreads per view, occ 4, 1024 CTAs)
// + diff precompute in a SEPARATE 16-B-cell plane:
//     g_ha[zg][v][d][8z] = half taps, g_hd[zg][v][d][8z] = half(a[d+1]-a[d])
//   Two cp.async.bulk per view (taps + diffs windows, one mbar, 2*WINB tx).
//   Inner loop drops HSUB2 (precomputed, bitwise-identical result).
// R12's 64-B cells reverted: 64-B stride caused 4-way LDS bank conflicts
// (16-B cell stride is mandatory).

#define NV   720
#define ND   1024
#define NVND (NV * ND)
#define NXI  512
#define NYI  512
#define WIN  80           // staged window cells per view (16-row tile: span ~67 + slack)
#define RY   4            // r-steps per thread (y stride 4) -> 16 y rows per warp
#define ZC   8            // z-slices per cell
#define WINB (WIN * 16)   // window bytes per plane = 1280
#define NBUF 2

__device__ float g_cos[NV];
__device__ float g_sin[NV];
// taps and diffs planes: each [zg][v][d][8z] half = 47.2 MB
__device__ __align__(16) __half g_ha[4ULL * NV * ND * 8];
__device__ __align__(16) __half g_hd[4ULL * NV * ND * 8];

// Convert: x[z][v][d] f32 -> g_ha (half taps), g_hd (half diffs vs d+1).
// Diff arithmetic == the old inner-loop HSUB2 -> bitwise-same lerp.
// Also fills trig tables.
__global__ __launch_bounds__(256) void convert_kernel(const float* __restrict__ x) {
    const int d  = blockIdx.x * 256 + threadIdx.x;
    const int v  = blockIdx.y;
    const int zg = blockIdx.z;
    if (zg == 0 && blockIdx.x == 0 && threadIdx.x == 0) {
        float th = (float)v * (float)(M_PI / (double)NV);
        g_cos[v] = cosf(th);
        g_sin[v] = sinf(th);
    }
    const int d1 = (d + 1 < ND) ? (d + 1) : (ND - 1);   // clamp; never sampled
    const float* __restrict__ b0 = x + (size_t)(zg * ZC) * NVND + (size_t)v * ND;

    unsigned ta[4], td[4];
#pragma unroll
    for (int j = 0; j < 4; j++) {
        float f0 = b0[(size_t)(2 * j)     * NVND + d];
        float f1 = b0[(size_t)(2 * j + 1) * NVND + d];
        float g0 = b0[(size_t)(2 * j)     * NVND + d1];
        float g1 = b0[(size_t)(2 * j + 1) * NVND + d1];
        __half2 ah = __floats2half2_rn(f0, f1);
        __half2 bh = __floats2half2_rn(g0, g1);
        __half2 dh = __hsub2(bh, ah);
        ta[j] = *reinterpret_cast<unsigned*>(&ah);
        td[j] = *reinterpret_cast<unsigned*>(&dh);
    }
    const size_t cidx = (((size_t)zg * NV + v) * ND + d) * 8;
    *reinterpret_cast<uint4*>(&g_ha[cidx]) = make_uint4(ta[0], ta[1], ta[2], ta[3]);
    *reinterpret_cast<uint4*>(&g_hd[cidx]) = make_uint4(td[0], td[1], td[2], td[3]);
}

// Must be computed identically by TMA issuer and consumers (same FP ops => it is).
__device__ __forceinline__ int calc_dmin(float c, float s, float xfmin, float yf0) {
    float xsel = (c >= 0.0f) ? xfmin : (xfmin + 63.0f);   // 64-wide x tile
    float tmin = fmaf(xsel, c, fmaf(yf0, s, 511.5f));     // s >= 0 on [0,pi)
    return (int)tmin - 1;                                 // tmin > 0: trunc==floor; -1 ulp guard
}

__device__ __forceinline__ void mbar_wait(unsigned mbar, unsigned phase) {
    unsigned done;
    do {
        asm volatile(
            "{\n\t.reg .pred p;\n\t"
            "mbarrier.try_wait.parity.acquire.cta.shared::cta.b64 p, [%1], %2, 0x989680;\n\t"
            "selp.b32 %0, 1, 0, p;\n\t}"
            : "=r"(done) : "r"(mbar), "r"(phase) : "memory");
    } while (!done);
}

// One view's staging: taps window + diffs window, single mbar (expect 2*WINB).
__device__ __forceinline__ void tma_fill2(unsigned dst_t, unsigned dst_d,
                                          const __half* src_t, const __half* src_d,
                                          unsigned full_mbar) {
    asm volatile("mbarrier.arrive.expect_tx.shared.b64 _, [%0], %1;"
                 :: "r"(full_mbar), "r"((unsigned)(2 * WINB)) : "memory");
    asm volatile("cp.async.bulk.shared::cta.global.mbarrier::complete_tx::bytes "
                 "[%0], [%1], %2, [%3];"
                 :: "r"(dst_t), "l"(src_t), "r"((unsigned)WINB), "r"(full_mbar)
                 : "memory");
    asm volatile("cp.async.bulk.shared::cta.global.mbarrier::complete_tx::bytes "
                 "[%0], [%1], %2, [%3];"
                 :: "r"(dst_d), "l"(src_d), "r"((unsigned)WINB), "r"(full_mbar)
                 : "memory");
}

__global__ __launch_bounds__(256, 4) void backproject_kernel(
    float* __restrict__ out)
{
    // [buf][plane][WINB]: plane 0 = taps, plane 1 = diffs (5 KB total)
    __shared__ __align__(16) char cellraw[NBUF][2][WINB];
    __shared__ float s_cos[NV], s_sin[NV];               // 5.76 KB
    __shared__ __align__(8) unsigned long long mbar[NBUF];

    const int tid  = threadIdx.x;            // 256 threads = 8 warps
    const int lane = tid & 31;
    const int wrp  = tid >> 5;
    const int lx   = lane & 7;               // 8 x per warp
    const int ly   = lane >> 3;              // 4 y per warp

    for (int i = tid; i < NV; i += 256) { s_cos[i] = g_cos[i]; s_sin[i] = g_sin[i]; }

    const int xg = blockIdx.x * 64 + wrp * 8 + lx;   // 8 x-tiles of 64
    const int yb = blockIdx.y * 16 + ly;             // 32 y-tiles of 16; rows yb + 4r
    const int zg = blockIdx.z;                       // 4 z-octs

    const float xf    = (float)xg - 255.5f;
    const float ybf   = (float)yb - 255.5f;
    const float xfmin = (float)(blockIdx.x * 64) - 255.5f;
    const float yf0   = (float)(blockIdx.y * 16) - 255.5f;

    float acc[RY][ZC];                       // persistent f32 accumulators (32 regs)
#pragma unroll
    for (int r = 0; r < RY; r++)
#pragma unroll
        for (int zz = 0; zz < ZC; zz++) acc[r][zz] = 0.0f;

    unsigned int cell_base, mbar_base;
    asm("{ .reg .u64 t; cvta.to.shared.u64 t, %1; cvt.u32.u64 %0, t; }"
        : "=r"(cell_base) : "l"((const void*)cellraw));
    asm("{ .reg .u64 t; cvta.to.shared.u64 t, %1; cvt.u32.u64 %0, t; }"
        : "=r"(mbar_base) : "l"((const void*)mbar));

    const __half* __restrict__ hza = &g_ha[(size_t)zg * NVND * 8];
    const __half* __restrict__ hzd = &g_hd[(size_t)zg * NVND * 8];

    if (tid == 0) {
        asm volatile("mbarrier.init.shared.b64 [%0], 1;" :: "r"(mbar_base)     : "memory");
        asm volatile("mbarrier.init.shared.b64 [%0], 1;" :: "r"(mbar_base + 8) : "memory");
    }
    __syncthreads();   // trig + mbarrier init visible

    if (tid == 0) {
        // Prime views 0 (exact c=1,s=0) and 1.
        int dm0 = calc_dmin(1.0f, 0.0f, xfmin, yf0);
        tma_fill2(cell_base, cell_base + WINB,
                  hza + (size_t)dm0 * 8, hzd + (size_t)dm0 * 8, mbar_base);
        int dm1 = calc_dmin(s_cos[1], s_sin[1], xfmin, yf0);
        tma_fill2(cell_base + 2 * WINB, cell_base + 3 * WINB,
                  hza + ((size_t)ND + dm1) * 8, hzd + ((size_t)ND + dm1) * 8,
                  mbar_base + 8);
    }

    for (int v = 0; v < NV; v++) {
        const int buf = v & 1;
        mbar_wait(mbar_base + buf * 8, (unsigned)((v >> 1) & 1));

        const float c = (v == 0) ? 1.0f : s_cos[v];
        const float s = (v == 0) ? 0.0f : s_sin[v];
        const int dmin = calc_dmin(c, s, xfmin, yf0);
        // u = t - dmin, in [0, WIN-2) for every pixel of this tile
        float u = fmaf(xf, c, fmaf(ybf, s, 511.5f - (float)dmin));
        const float s4 = 4.0f * s;                 // y stride 4 rows per r-step
        const unsigned int base_t = cell_base + (unsigned)(buf * 2 * WINB);

#pragma unroll
        for (int r = 0; r < RY; r++) {
            int   i0 = (int)u;                     // u > 0: trunc == floor
            float w  = u - (float)i0;
            __half2 wh2 = __float2half2_rn(w);     // one F2FP (broadcast pack)
            unsigned int a0 = base_t + (unsigned)i0 * 16u;
            uint4 A, D;
            asm("ld.shared.v4.b32 {%0,%1,%2,%3}, [%4];"
                : "=r"(A.x), "=r"(A.y), "=r"(A.z), "=r"(A.w) : "r"(a0));
            asm("ld.shared.v4.b32 {%0,%1,%2,%3}, [%4 + 1280];"   // diffs plane
                : "=r"(D.x), "=r"(D.y), "=r"(D.z), "=r"(D.w) : "r"(a0));
#pragma unroll
            for (int p = 0; p < 4; p++) {
                unsigned ua = (p == 0) ? A.x : (p == 1) ? A.y : (p == 2) ? A.z : A.w;
                unsigned ud = (p == 0) ? D.x : (p == 1) ? D.y : (p == 2) ? D.z : D.w;
                __half2 ha = *reinterpret_cast<__half2*>(&ua);
                __half2 hd = *reinterpret_cast<__half2*>(&ud);
                // l = a + w*diff (diff precomputed == old HSUB2 result)
                __half2 l  = __hfma2(hd, wh2, ha);
                float2 f   = __half22float2(l);
                acc[r][2 * p]     += f.x;
                acc[r][2 * p + 1] += f.y;
            }
            u += s4;
        }

        __syncthreads();   // all threads done reading buf before refilling it

        if (v + 2 < NV && tid == 0) {
            float c2 = s_cos[v + 2], s2 = s_sin[v + 2];
            int dm = calc_dmin(c2, s2, xfmin, yf0);
            tma_fill2(base_t, base_t + WINB,
                      hza + ((size_t)(v + 2) * ND + dm) * 8,
                      hzd + ((size_t)(v + 2) * ND + dm) * 8,
                      mbar_base + buf * 8);
        }
    }

    const float scale = (float)(M_PI / (double)NV);
#pragma unroll
    for (int r = 0; r < RY; r++) {
        const int y = yb + 4 * r;
#pragma unroll
        for (int zz = 0; zz < ZC; zz++) {
            out[((size_t)(zg * ZC + zz) * NYI + y) * NXI + xg] = acc[r][zz] * scale;
        }
    }
}

extern "C" void kernel_launch(void* const* d_in, const int* in_sizes, int n_in,
                              void* d_out, int out_size)
{
    const float* x   = (const float*)d_in[0];
    float*       out = (float*)d_out;

    convert_kernel<<<dim3(ND / 256, NV, 4), 256>>>(x);

    dim3 grid(8, 32, 4);   // x-tiles, y-tiles, z-octs = 1024 CTAs
    backproject_kernel<<<grid, 256>>>(out);
}